// round 15
// baseline (speedup 1.0000x reference)
#include <cuda_runtime.h>
#include <cuda_fp16.h>
#include <math_constants.h>
#include <cstdint>

#define SEQ 2048
#define DMODEL 1024
#define NB 2
#define NH 16
#define DH 64

// Scratch (__device__ globals: allocations are forbidden)
__device__ __half g_xh[NB*SEQ*DMODEL];    // fp16 copy of x
__device__ __half g_Wqh[DMODEL*DMODEL];
__device__ __half g_Wkh[DMODEL*DMODEL];
__device__ __half g_Wvh[DMODEL*DMODEL];
__device__ __half g_Woh[DMODEL*DMODEL];
__device__ __half g_Qh[NB*NH*SEQ*DH];     // [B,H,S,Dh], pre-scaled by log2e/8
__device__ __half g_Kh[NB*NH*SEQ*DH];
__device__ __half g_Vh[NB*NH*SEQ*DH];
__device__ __half g_ctxh[NB*SEQ*DMODEL];  // [B,S,D]
__device__ float2 g_rope[SEQ*32];         // [s][j] = (sin, cos)

// ============================ PTX helpers ==================================
__device__ __forceinline__ uint32_t smem_u32(const void* p) {
    uint32_t a;
    asm("{ .reg .u64 t; cvta.to.shared.u64 t, %1; cvt.u32.u64 %0, t; }"
        : "=r"(a) : "l"(p));
    return a;
}
__device__ __forceinline__ void cp16(uint32_t dst, const void* src) {
    asm volatile("cp.async.cg.shared.global [%0], [%1], 16;"
                 :: "r"(dst), "l"(src) : "memory");
}
#define CP_COMMIT() asm volatile("cp.async.commit_group;" ::: "memory")
#define CP_WAIT(n)  asm volatile("cp.async.wait_group %0;" :: "n"(n) : "memory")

#define LDSM4(r0, r1, r2, r3, addr)                                          \
    asm volatile("ldmatrix.sync.aligned.m8n8.x4.shared.b16 {%0,%1,%2,%3}, [%4];" \
                 : "=r"(r0), "=r"(r1), "=r"(r2), "=r"(r3) : "r"(addr))
#define LDSM4T(r0, r1, r2, r3, addr)                                         \
    asm volatile("ldmatrix.sync.aligned.m8n8.x4.trans.shared.b16 {%0,%1,%2,%3}, [%4];" \
                 : "=r"(r0), "=r"(r1), "=r"(r2), "=r"(r3) : "r"(addr))

// D(f32) += A(16x16 f16, row) * B(16x8 f16, col)
__device__ __forceinline__ void mma16(float* c, const uint32_t* a,
                                      uint32_t b0, uint32_t b1) {
    asm volatile(
        "mma.sync.aligned.m16n8k16.row.col.f32.f16.f16.f32 "
        "{%0,%1,%2,%3}, {%4,%5,%6,%7}, {%8,%9}, {%0,%1,%2,%3};"
        : "+f"(c[0]), "+f"(c[1]), "+f"(c[2]), "+f"(c[3])
        : "r"(a[0]), "r"(a[1]), "r"(a[2]), "r"(a[3]), "r"(b0), "r"(b1));
}
__device__ __forceinline__ uint32_t packh2(float lo, float hi) {
    half2 h = __floats2half2_rn(lo, hi);
    return reinterpret_cast<uint32_t&>(h);
}
__device__ __forceinline__ float ex2(float x) {
    float r;
    asm("ex2.approx.f32 %0, %1;" : "=f"(r) : "f"(x));
    return r;
}

// ============================ init kernel ==================================
// z 0..3: quarters of x -> fp16.  z 4..7: Wq,Wk,Wv,Wo -> fp16.
// z == 8: RoPE sin/cos table (first 256 blocks only).
__global__ void cvt_init(const float* __restrict__ x,  const float* __restrict__ wq,
                         const float* __restrict__ wk, const float* __restrict__ wv,
                         const float* __restrict__ wo) {
    int z = blockIdx.z;
    if (z == 8) {
        int i = blockIdx.x * 256 + threadIdx.x;
        if (i < SEQ * 32) {
            int s = i >> 5, j = i & 31;
            const float LN1E4_OVER_32 = 0.28782313662425575f;
            float inv = expf(-LN1E4_OVER_32 * (float)j);
            float sn, cs;
            sincosf((float)s * inv, &sn, &cs);
            g_rope[i] = make_float2(sn, cs);
        }
        return;
    }
    int i = (blockIdx.x * 256 + threadIdx.x) * 4;   // < 1048576
    const float* src;
    __half* dst;
    if (z < 4)      { src = x + (size_t)z * 1048576; dst = g_xh + (size_t)z * 1048576; }
    else if (z == 4){ src = wq; dst = g_Wqh; }
    else if (z == 5){ src = wk; dst = g_Wkh; }
    else if (z == 6){ src = wv; dst = g_Wvh; }
    else            { src = wo; dst = g_Woh; }
    float4 v = *(const float4*)(src + i);
    *(half2*)(dst + i)     = __floats2half2_rn(v.x, v.y);
    *(half2*)(dst + i + 2) = __floats2half2_rn(v.z, v.w);
}

// ---------------------------------------------------------------------------
// fp16 mma GEMM: C[Mx1024] = A[Mx1024] @ W[1024x1024]^T (both K-contiguous)
// 128x128 CTA tile, 8 warps 4x2 (each 32m x 64n), k-chunk 64 (128B rows,
// SW128 xor swizzle), 3-stage cp.async ring with early prefetch issue.
// mode 0: Q proj (x log2e/8) + RoPE -> g_Qh   mode 1: K proj + RoPE -> g_Kh
// mode 2: V proj -> g_Vh                      mode 3: g_ctxh @ Wo^T -> outp
// ---------------------------------------------------------------------------
#define GSTG 32768
__global__ __launch_bounds__(256, 2) void gemm_h(
    const __half* __restrict__ Ag, const __half* __restrict__ W0,
    const __half* __restrict__ W1, const __half* __restrict__ W2,
    float* __restrict__ outp, int mode_base)
{
    extern __shared__ char smc[];
    const uint32_t smu = smem_u32(smc);
    const int mode = mode_base + blockIdx.z;
    const __half* Wg = (mode == 1) ? W1 : (mode == 2) ? W2 : W0;

    const int tid = threadIdx.x, w = tid >> 5, lane = tid & 31;
    const int gi = lane >> 2, tg = lane & 3;
    const int rw = lane & 7, bq = lane >> 3;
    const int wr = w >> 1, wc = w & 1;
    const int m0 = blockIdx.y << 7, n0 = blockIdx.x << 7;
    const __half* gA = Ag + (size_t)m0 * 1024;
    const __half* gW = Wg + (size_t)n0 * 1024;

    auto load_stage = [&](int st, int kc) {
        uint32_t dA = smu + st * GSTG;
        uint32_t dB = dA + 16384;
        const int k0 = kc << 6;
#pragma unroll
        for (int i = 0; i < 4; ++i) {
            int g = tid + (i << 8);             // 0..1023
            int row = g >> 3, ch = g & 7;
            uint32_t sw = (uint32_t)(ch ^ (row & 7)) << 4;
            cp16(dA + row * 128 + sw, gA + (size_t)row * 1024 + k0 + ch * 8);
            cp16(dB + row * 128 + sw, gW + (size_t)row * 1024 + k0 + ch * 8);
        }
        CP_COMMIT();
    };

    load_stage(0, 0);
    load_stage(1, 1);

    float acc[2][8][4] = {};

    for (int c = 0; c < 16; ++c) {
        if (c < 15) { CP_WAIT(1); } else { CP_WAIT(0); }
        __syncthreads();
        if (c + 2 < 16) load_stage((c + 2) % 3, c + 2);

        uint32_t bA = smu + (c % 3) * GSTG;
        uint32_t bB = bA + 16384;
#pragma unroll
        for (int kc = 0; kc < 4; ++kc) {
            uint32_t a[2][4];
#pragma unroll
            for (int mf = 0; mf < 2; ++mf) {
                int row = wr * 32 + mf * 16 + (bq & 1) * 8 + rw;
                int kch = kc * 2 + (bq >> 1);
                LDSM4(a[mf][0], a[mf][1], a[mf][2], a[mf][3],
                      bA + row * 128 + ((uint32_t)(kch ^ (row & 7)) << 4));
            }
            uint32_t b[8][2];
#pragma unroll
            for (int np = 0; np < 4; ++np) {
                int row = wc * 64 + np * 16 + (bq >> 1) * 8 + rw;
                int kch = kc * 2 + (bq & 1);
                LDSM4(b[2*np][0], b[2*np][1], b[2*np+1][0], b[2*np+1][1],
                      bB + row * 128 + ((uint32_t)(kch ^ (row & 7)) << 4));
            }
#pragma unroll
            for (int nf = 0; nf < 8; ++nf) {
                mma16(acc[0][nf], a[0], b[nf][0], b[nf][1]);
                mma16(acc[1][nf], a[1], b[nf][0], b[nf][1]);
            }
        }
    }

    // ---- epilogues ----------------------------------------------------------
    if (mode == 3) {
#pragma unroll
        for (int mf = 0; mf < 2; ++mf) {
            int m = m0 + wr * 32 + mf * 16 + gi;
            float* d0 = outp + (size_t)m * 1024 + n0 + wc * 64;
            float* d1 = d0 + 8 * 1024;
#pragma unroll
            for (int nf = 0; nf < 8; ++nf) {
                *(float2*)(d0 + nf * 8 + 2 * tg) = make_float2(acc[mf][nf][0], acc[mf][nf][1]);
                *(float2*)(d1 + nf * 8 + 2 * tg) = make_float2(acc[mf][nf][2], acc[mf][nf][3]);
            }
        }
        return;
    }

    const int h = (n0 >> 6) + wc;
    __half* out = (mode == 0) ? g_Qh : (mode == 1) ? g_Kh : g_Vh;

    if (mode == 2) {
#pragma unroll
        for (int mf = 0; mf < 2; ++mf) {
            int m = m0 + wr * 32 + mf * 16 + gi;
            int b = m >> 11, s = m & 2047;
            __half* d0 = out + ((size_t)((b << 4) + h) * SEQ + s) * DH;
            __half* d1 = d0 + 8 * DH;
#pragma unroll
            for (int nf = 0; nf < 8; ++nf) {
                *(half2*)(d0 + nf * 8 + 2 * tg) = __floats2half2_rn(acc[mf][nf][0], acc[mf][nf][1]);
                *(half2*)(d1 + nf * 8 + 2 * tg) = __floats2half2_rn(acc[mf][nf][2], acc[mf][nf][3]);
            }
        }
        return;
    }

    // RoPE: thread holds (x[2j], x[2j+1]) pairs, j = nf*4 + tg.
    //   dst[j] = x0*cos - x1*sin ; dst[j+32] = x0*sin + x1*cos
    // mode 0 pre-scales Q by log2e/sqrt(Dh) (log2-domain softmax-free path).
    const float qsc = (mode == 0) ? 0.18033688011112043f : 1.0f;
#pragma unroll
    for (int mf = 0; mf < 2; ++mf) {
        int m = m0 + wr * 32 + mf * 16 + gi;
        int b = m >> 11, s = m & 2047;
        const float2* tb0 = g_rope + s * 32;
        const float2* tb1 = g_rope + (s + 8) * 32;
        __half* d0 = out + ((size_t)((b << 4) + h) * SEQ + s) * DH;
        __half* d1 = d0 + 8 * DH;
#pragma unroll
        for (int nf = 0; nf < 8; ++nf) {
            int j = nf * 4 + tg;
            float2 sc0 = tb0[j], sc1 = tb1[j];
            float x0 = acc[mf][nf][0] * qsc, x1 = acc[mf][nf][1] * qsc;
            d0[j]      = __float2half_rn(x0 * sc0.y - x1 * sc0.x);
            d0[j + 32] = __float2half_rn(x0 * sc0.x + x1 * sc0.y);
            float y0 = acc[mf][nf][2] * qsc, y1 = acc[mf][nf][3] * qsc;
            d1[j]      = __float2half_rn(y0 * sc1.y - y1 * sc1.x);
            d1[j + 32] = __float2half_rn(y0 * sc1.x + y1 * sc1.y);
        }
    }
}

// ---------------------------------------------------------------------------
// fp16 flash attention, softmax-free, CROSS-TILE SOFTWARE PIPELINED:
// iteration t packs P_t = exp2(S_t), then interleaves the QK mmas of tile
// t+1 with the PV mmas of tile t (independent streams -> MUFU and tensor
// pipe overlap instead of serializing). One CTA = (b, h, 128 q), 8 warps x
// 16 q-rows, key tile 64, 4-stage cp.async K/V ring.
// Smem: Q 16KB + 4 x 16KB = 80KB -> 2 CTAs/SM.
// ---------------------------------------------------------------------------
__global__ __launch_bounds__(256, 2) void attn_h()
{
    extern __shared__ char smc[];
    const uint32_t smu = smem_u32(smc);
    const uint32_t Qs = smu;                      // 128 rows x 128B

    const int tid = threadIdx.x, w = tid >> 5, lane = tid & 31;
    const int gi = lane >> 2, tg = lane & 3;
    const int rw = lane & 7, bq = lane >> 3;
    const int qt = blockIdx.x, h = blockIdx.y, b = blockIdx.z;
    const int bh = (b << 4) + h;
    const uint32_t ONES = 0x3C003C00u;            // half2(1.0, 1.0)

    const __half* Qg = g_Qh + ((size_t)bh * SEQ + (qt << 7)) * DH;
    const __half* Kg = g_Kh + (size_t)bh * SEQ * DH;
    const __half* Vg = g_Vh + (size_t)bh * SEQ * DH;

    // Q: 1024 granules of 16B (group 0)
#pragma unroll
    for (int i = 0; i < 4; ++i) {
        int g = tid + (i << 8);
        int row = g >> 3, ch = g & 7;
        cp16(Qs + row * 128 + ((uint32_t)(ch ^ (row & 7)) << 4),
             Qg + (size_t)row * 64 + ch * 8);
    }
    CP_COMMIT();

    auto load_kv = [&](int st, int kt) {
        uint32_t Kb = smu + 16384 + st * 16384;
        uint32_t Vb = Kb + 8192;
        const __half* kp = Kg + (size_t)(kt << 6) * DH;
        const __half* vp = Vg + (size_t)(kt << 6) * DH;
#pragma unroll
        for (int i = 0; i < 2; ++i) {
            int g = tid + (i << 8);
            int row = g >> 3, ch = g & 7;
            uint32_t sw = (uint32_t)(ch ^ (row & 7)) << 4;
            cp16(Kb + row * 128 + sw, kp + (size_t)row * 64 + ch * 8);
            cp16(Vb + row * 128 + sw, vp + (size_t)row * 64 + ch * 8);
        }
        CP_COMMIT();
    };
    load_kv(0, 0);
    load_kv(1, 1);
    load_kv(2, 2);

    CP_WAIT(2);            // Q + kv0 complete
    __syncthreads();

    // Hoist Q fragments (reused for all 32 tiles)
    uint32_t Aq[4][4];
#pragma unroll
    for (int kc = 0; kc < 4; ++kc) {
        int row = w * 16 + (bq & 1) * 8 + rw;
        int kch = kc * 2 + (bq >> 1);
        LDSM4(Aq[kc][0], Aq[kc][1], Aq[kc][2], Aq[kc][3],
              Qs + row * 128 + ((uint32_t)(kch ^ (row & 7)) << 4));
    }

    float S[8][4] = {};
    // Prologue: S for tile 0 (buffer 0)
    {
        uint32_t Kb = smu + 16384;
#pragma unroll
        for (int kc = 0; kc < 4; ++kc) {
            uint32_t bK[8][2];
#pragma unroll
            for (int np = 0; np < 4; ++np) {
                int row = np * 16 + (bq >> 1) * 8 + rw;
                int kch = kc * 2 + (bq & 1);
                LDSM4(bK[2*np][0], bK[2*np][1], bK[2*np+1][0], bK[2*np+1][1],
                      Kb + row * 128 + ((uint32_t)(kch ^ (row & 7)) << 4));
            }
#pragma unroll
            for (int nf = 0; nf < 8; ++nf)
                mma16(S[nf], Aq[kc], bK[nf][0], bK[nf][1]);
        }
    }

    float O[8][4] = {};
    float L[4] = {};        // ones-mma row sums; L[0]: row gi, L[2]: row gi+8

    for (int t = 0; t < 32; ++t) {
        // Pack P_t = exp2(S_t) into fp16 A-frags; free S for tile t+1.
        uint32_t Ap[4][4];
#pragma unroll
        for (int kc = 0; kc < 4; ++kc) {
            Ap[kc][0] = packh2(ex2(S[2*kc][0]),   ex2(S[2*kc][1]));
            Ap[kc][1] = packh2(ex2(S[2*kc][2]),   ex2(S[2*kc][3]));
            Ap[kc][2] = packh2(ex2(S[2*kc+1][0]), ex2(S[2*kc+1][1]));
            Ap[kc][3] = packh2(ex2(S[2*kc+1][2]), ex2(S[2*kc+1][3]));
#pragma unroll
            for (int i = 0; i < 4; ++i) { S[2*kc][i] = 0.f; S[2*kc+1][i] = 0.f; }
        }

        // Ensure kv(t+1) is resident for the interleaved QK-next stream.
        if (t < 30)      { CP_WAIT(1); }
        else if (t == 30){ CP_WAIT(0); }
        __syncthreads();
        if (t + 3 < 32) load_kv((t + 3) & 3, t + 3);

        uint32_t Vb = smu + 16384 + (t & 3) * 16384 + 8192;       // V of tile t
        uint32_t Kn = smu + 16384 + ((t + 1) & 3) * 16384;        // K of tile t+1
        const bool more = (t < 31);

        // Interleaved: QK(t+1) + L(t) + PV(t)
#pragma unroll
        for (int kc = 0; kc < 4; ++kc) {
            if (more) {
                uint32_t bK[8][2];
#pragma unroll
                for (int np = 0; np < 4; ++np) {
                    int row = np * 16 + (bq >> 1) * 8 + rw;
                    int kch = kc * 2 + (bq & 1);
                    LDSM4(bK[2*np][0], bK[2*np][1], bK[2*np+1][0], bK[2*np+1][1],
                          Kn + row * 128 + ((uint32_t)(kch ^ (row & 7)) << 4));
                }
#pragma unroll
                for (int nf = 0; nf < 8; ++nf)
                    mma16(S[nf], Aq[kc], bK[nf][0], bK[nf][1]);
            }
            mma16(L, Ap[kc], ONES, ONES);   // exact fp32 row sums, tensor pipe
#pragma unroll
            for (int dp = 0; dp < 4; ++dp) {
                uint32_t r0, r1, r2, r3;
                int krow = kc * 16 + (bq & 1) * 8 + rw;
                int dch = dp * 2 + (bq >> 1);
                LDSM4T(r0, r1, r2, r3,
                       Vb + krow * 128 + ((uint32_t)(dch ^ (krow & 7)) << 4));
                mma16(O[2*dp],     Ap[kc], r0, r1);
                mma16(O[2*dp + 1], Ap[kc], r2, r3);
            }
        }
    }

    // Normalize, store ctx (fp16, head-merged [B,S,D])
    float inv0 = 1.0f / L[0], inv1 = 1.0f / L[2];
    int r = (qt << 7) + w * 16 + gi;
    __half* d0 = g_ctxh + ((size_t)b * SEQ + r) * DMODEL + (h << 6);
    __half* d1 = d0 + 8 * DMODEL;
#pragma unroll
    for (int nf = 0; nf < 8; ++nf) {
        *(half2*)(d0 + nf * 8 + 2 * tg) = __floats2half2_rn(O[nf][0] * inv0, O[nf][1] * inv0);
        *(half2*)(d1 + nf * 8 + 2 * tg) = __floats2half2_rn(O[nf][2] * inv1, O[nf][3] * inv1);
    }
}

// ---------------------------------------------------------------------------
extern "C" void kernel_launch(void* const* d_in, const int* in_sizes, int n_in,
                              void* d_out, int out_size)
{
    const float* x  = (const float*)d_in[0];
    const float* Wq = (const float*)d_in[1];
    const float* Wk = (const float*)d_in[2];
    const float* Wv = (const float*)d_in[3];
    const float* Wo = (const float*)d_in[4];
    float* out = (float*)d_out;

    const int GEMM_SMEM = 3 * GSTG;            // 98304 B
    const int ATTN_SMEM = 16384 + 4 * 16384;   // 81920 B
    static int inited = 0;
    if (!inited) {
        cudaFuncSetAttribute(gemm_h, cudaFuncAttributeMaxDynamicSharedMemorySize, GEMM_SMEM);
        cudaFuncSetAttribute(attn_h, cudaFuncAttributeMaxDynamicSharedMemorySize, ATTN_SMEM);
        inited = 1;
    }

    // device-pointer fetches for __device__ globals used as kernel args
    __half *xh, *wqh, *wkh, *wvh, *woh, *ctxh;
    cudaGetSymbolAddress((void**)&xh,   g_xh);
    cudaGetSymbolAddress((void**)&wqh,  g_Wqh);
    cudaGetSymbolAddress((void**)&wkh,  g_Wkh);
    cudaGetSymbolAddress((void**)&wvh,  g_Wvh);
    cudaGetSymbolAddress((void**)&woh,  g_Woh);
    cudaGetSymbolAddress((void**)&ctxh, g_ctxh);

    cvt_init<<<dim3(1024, 1, 9), 256>>>(x, Wq, Wk, Wv, Wo);
    // fused Q/K/V projections: z = mode 0,1,2
    gemm_h<<<dim3(8, 32, 3), 256, GEMM_SMEM>>>(xh, wqh, wkh, wvh, nullptr, 0);
    attn_h<<<dim3(16, NH, NB), 256, ATTN_SMEM>>>();
    gemm_h<<<dim3(8, 32, 1), 256, GEMM_SMEM>>>(ctxh, woh, nullptr, nullptr, out, 3);
}

// round 17
// speedup vs baseline: 1.1025x; 1.1025x over previous
#include <cuda_runtime.h>
#include <cuda_fp16.h>
#include <math_constants.h>
#include <cstdint>

#define SEQ 2048
#define DMODEL 1024
#define NB 2
#define NH 16
#define DH 64

// Scratch (__device__ globals: allocations are forbidden)
__device__ __half g_xh[NB*SEQ*DMODEL];    // fp16 copy of x
__device__ __half g_Wqh[DMODEL*DMODEL];
__device__ __half g_Wkh[DMODEL*DMODEL];
__device__ __half g_Wvh[DMODEL*DMODEL];
__device__ __half g_Woh[DMODEL*DMODEL];
__device__ __half g_Qh[NB*NH*SEQ*DH];     // [B,H,S,Dh], pre-scaled by log2e/8
__device__ __half g_Kh[NB*NH*SEQ*DH];
__device__ __half g_Vh[NB*NH*SEQ*DH];
__device__ __half g_ctxh[NB*SEQ*DMODEL];  // [B,S,D]
__device__ float2 g_rope[SEQ*32];         // [s][j] = (sin, cos)

// ============================ PTX helpers ==================================
__device__ __forceinline__ uint32_t smem_u32(const void* p) {
    uint32_t a;
    asm("{ .reg .u64 t; cvta.to.shared.u64 t, %1; cvt.u32.u64 %0, t; }"
        : "=r"(a) : "l"(p));
    return a;
}
__device__ __forceinline__ void cp16(uint32_t dst, const void* src) {
    asm volatile("cp.async.cg.shared.global [%0], [%1], 16;"
                 :: "r"(dst), "l"(src) : "memory");
}
#define CP_COMMIT() asm volatile("cp.async.commit_group;" ::: "memory")
#define CP_WAIT(n)  asm volatile("cp.async.wait_group %0;" :: "n"(n) : "memory")

#define LDSM4(r0, r1, r2, r3, addr)                                          \
    asm volatile("ldmatrix.sync.aligned.m8n8.x4.shared.b16 {%0,%1,%2,%3}, [%4];" \
                 : "=r"(r0), "=r"(r1), "=r"(r2), "=r"(r3) : "r"(addr))
#define LDSM4T(r0, r1, r2, r3, addr)                                         \
    asm volatile("ldmatrix.sync.aligned.m8n8.x4.trans.shared.b16 {%0,%1,%2,%3}, [%4];" \
                 : "=r"(r0), "=r"(r1), "=r"(r2), "=r"(r3) : "r"(addr))

// D(f32) += A(16x16 f16, row) * B(16x8 f16, col)
__device__ __forceinline__ void mma16(float* c, const uint32_t* a,
                                      uint32_t b0, uint32_t b1) {
    asm volatile(
        "mma.sync.aligned.m16n8k16.row.col.f32.f16.f16.f32 "
        "{%0,%1,%2,%3}, {%4,%5,%6,%7}, {%8,%9}, {%0,%1,%2,%3};"
        : "+f"(c[0]), "+f"(c[1]), "+f"(c[2]), "+f"(c[3])
        : "r"(a[0]), "r"(a[1]), "r"(a[2]), "r"(a[3]), "r"(b0), "r"(b1));
}
__device__ __forceinline__ uint32_t packh2(float lo, float hi) {
    half2 h = __floats2half2_rn(lo, hi);
    return reinterpret_cast<uint32_t&>(h);
}
__device__ __forceinline__ float ex2(float x) {
    float r;
    asm("ex2.approx.f32 %0, %1;" : "=f"(r) : "f"(x));
    return r;
}

// ============================ init kernel ==================================
// z 0..3: quarters of x -> fp16.  z 4..7: Wq,Wk,Wv,Wo -> fp16.
// z == 8: RoPE sin/cos table (first 256 blocks only).
__global__ void cvt_init(const float* __restrict__ x,  const float* __restrict__ wq,
                         const float* __restrict__ wk, const float* __restrict__ wv,
                         const float* __restrict__ wo) {
    int z = blockIdx.z;
    if (z == 8) {
        int i = blockIdx.x * 256 + threadIdx.x;
        if (i < SEQ * 32) {
            int s = i >> 5, j = i & 31;
            const float LN1E4_OVER_32 = 0.28782313662425575f;
            float inv = expf(-LN1E4_OVER_32 * (float)j);
            float sn, cs;
            sincosf((float)s * inv, &sn, &cs);
            g_rope[i] = make_float2(sn, cs);
        }
        return;
    }
    int i = (blockIdx.x * 256 + threadIdx.x) * 4;   // < 1048576
    const float* src;
    __half* dst;
    if (z < 4)      { src = x + (size_t)z * 1048576; dst = g_xh + (size_t)z * 1048576; }
    else if (z == 4){ src = wq; dst = g_Wqh; }
    else if (z == 5){ src = wk; dst = g_Wkh; }
    else if (z == 6){ src = wv; dst = g_Wvh; }
    else            { src = wo; dst = g_Woh; }
    float4 v = *(const float4*)(src + i);
    *(half2*)(dst + i)     = __floats2half2_rn(v.x, v.y);
    *(half2*)(dst + i + 2) = __floats2half2_rn(v.z, v.w);
}

// ---------------------------------------------------------------------------
// fp16 mma GEMM (unchanged from the 215.6us config): C = A @ W^T,
// 128x128 CTA tile, 8 warps 4x2, k-chunk 64 (SW128 swizzle), 3-stage
// cp.async ring (prefetch issued after compute).
// mode 0: Q proj (x log2e/8) + RoPE -> g_Qh   mode 1: K proj + RoPE -> g_Kh
// mode 2: V proj -> g_Vh                      mode 3: g_ctxh @ Wo^T -> outp
// ---------------------------------------------------------------------------
#define GSTG 32768
__global__ __launch_bounds__(256, 2) void gemm_h(
    const __half* __restrict__ Ag, const __half* __restrict__ W0,
    const __half* __restrict__ W1, const __half* __restrict__ W2,
    float* __restrict__ outp, int mode_base)
{
    extern __shared__ char smc[];
    const uint32_t smu = smem_u32(smc);
    const int mode = mode_base + blockIdx.z;
    const __half* Wg = (mode == 1) ? W1 : (mode == 2) ? W2 : W0;

    const int tid = threadIdx.x, w = tid >> 5, lane = tid & 31;
    const int gi = lane >> 2, tg = lane & 3;
    const int rw = lane & 7, bq = lane >> 3;
    const int wr = w >> 1, wc = w & 1;
    const int m0 = blockIdx.y << 7, n0 = blockIdx.x << 7;
    const __half* gA = Ag + (size_t)m0 * 1024;
    const __half* gW = Wg + (size_t)n0 * 1024;

    auto load_stage = [&](int st, int kc) {
        uint32_t dA = smu + st * GSTG;
        uint32_t dB = dA + 16384;
        const int k0 = kc << 6;
#pragma unroll
        for (int i = 0; i < 4; ++i) {
            int g = tid + (i << 8);             // 0..1023
            int row = g >> 3, ch = g & 7;
            uint32_t sw = (uint32_t)(ch ^ (row & 7)) << 4;
            cp16(dA + row * 128 + sw, gA + (size_t)row * 1024 + k0 + ch * 8);
            cp16(dB + row * 128 + sw, gW + (size_t)row * 1024 + k0 + ch * 8);
        }
        CP_COMMIT();
    };

    load_stage(0, 0);
    load_stage(1, 1);

    float acc[2][8][4] = {};

    for (int c = 0; c < 16; ++c) {
        if (c < 15) { CP_WAIT(1); } else { CP_WAIT(0); }
        __syncthreads();
        uint32_t bA = smu + (c % 3) * GSTG;
        uint32_t bB = bA + 16384;
#pragma unroll
        for (int kc = 0; kc < 4; ++kc) {
            uint32_t a[2][4];
#pragma unroll
            for (int mf = 0; mf < 2; ++mf) {
                int row = wr * 32 + mf * 16 + (bq & 1) * 8 + rw;
                int kch = kc * 2 + (bq >> 1);
                LDSM4(a[mf][0], a[mf][1], a[mf][2], a[mf][3],
                      bA + row * 128 + ((uint32_t)(kch ^ (row & 7)) << 4));
            }
            uint32_t b[8][2];
#pragma unroll
            for (int np = 0; np < 4; ++np) {
                int row = wc * 64 + np * 16 + (bq >> 1) * 8 + rw;
                int kch = kc * 2 + (bq & 1);
                LDSM4(b[2*np][0], b[2*np][1], b[2*np+1][0], b[2*np+1][1],
                      bB + row * 128 + ((uint32_t)(kch ^ (row & 7)) << 4));
            }
#pragma unroll
            for (int nf = 0; nf < 8; ++nf) {
                mma16(acc[0][nf], a[0], b[nf][0], b[nf][1]);
                mma16(acc[1][nf], a[1], b[nf][0], b[nf][1]);
            }
        }
        if (c + 2 < 16) load_stage((c + 2) % 3, c + 2);
    }

    // ---- epilogues ----------------------------------------------------------
    if (mode == 3) {
#pragma unroll
        for (int mf = 0; mf < 2; ++mf) {
            int m = m0 + wr * 32 + mf * 16 + gi;
            float* d0 = outp + (size_t)m * 1024 + n0 + wc * 64;
            float* d1 = d0 + 8 * 1024;
#pragma unroll
            for (int nf = 0; nf < 8; ++nf) {
                *(float2*)(d0 + nf * 8 + 2 * tg) = make_float2(acc[mf][nf][0], acc[mf][nf][1]);
                *(float2*)(d1 + nf * 8 + 2 * tg) = make_float2(acc[mf][nf][2], acc[mf][nf][3]);
            }
        }
        return;
    }

    const int h = (n0 >> 6) + wc;
    __half* out = (mode == 0) ? g_Qh : (mode == 1) ? g_Kh : g_Vh;

    if (mode == 2) {
#pragma unroll
        for (int mf = 0; mf < 2; ++mf) {
            int m = m0 + wr * 32 + mf * 16 + gi;
            int b = m >> 11, s = m & 2047;
            __half* d0 = out + ((size_t)((b << 4) + h) * SEQ + s) * DH;
            __half* d1 = d0 + 8 * DH;
#pragma unroll
            for (int nf = 0; nf < 8; ++nf) {
                *(half2*)(d0 + nf * 8 + 2 * tg) = __floats2half2_rn(acc[mf][nf][0], acc[mf][nf][1]);
                *(half2*)(d1 + nf * 8 + 2 * tg) = __floats2half2_rn(acc[mf][nf][2], acc[mf][nf][3]);
            }
        }
        return;
    }

    // RoPE: thread holds (x[2j], x[2j+1]) pairs, j = nf*4 + tg.
    const float qsc = (mode == 0) ? 0.18033688011112043f : 1.0f;
#pragma unroll
    for (int mf = 0; mf < 2; ++mf) {
        int m = m0 + wr * 32 + mf * 16 + gi;
        int b = m >> 11, s = m & 2047;
        const float2* tb0 = g_rope + s * 32;
        const float2* tb1 = g_rope + (s + 8) * 32;
        __half* d0 = out + ((size_t)((b << 4) + h) * SEQ + s) * DH;
        __half* d1 = d0 + 8 * DH;
#pragma unroll
        for (int nf = 0; nf < 8; ++nf) {
            int j = nf * 4 + tg;
            float2 sc0 = tb0[j], sc1 = tb1[j];
            float x0 = acc[mf][nf][0] * qsc, x1 = acc[mf][nf][1] * qsc;
            d0[j]      = __float2half_rn(x0 * sc0.y - x1 * sc0.x);
            d0[j + 32] = __float2half_rn(x0 * sc0.x + x1 * sc0.y);
            float y0 = acc[mf][nf][2] * qsc, y1 = acc[mf][nf][3] * qsc;
            d1[j]      = __float2half_rn(y0 * sc1.y - y1 * sc1.x);
            d1[j + 32] = __float2half_rn(y0 * sc1.x + y1 * sc1.y);
        }
    }
}

// ---------------------------------------------------------------------------
// fp16 flash attention, softmax-free, M=32 PER WARP. One CTA = (b, h, 128
// q-rows) with 4 warps x 32 q-rows (two m16 tiles per warp) -> each K/V
// fragment load feeds 2x the mma work, halving per-SM LDSM traffic (the
// measured L1 bottleneck). 128 threads, __launch_bounds__(128,2) -> 252-reg
// budget, 2 CTAs/SM, 8 warps/SM. Phase-serial per-kc pipeline identical to
// the proven R13 structure (pack Ap per kc -> L mma -> PV mmas), just with
// an mf dimension. Key tile 64, 32 tiles, 4-stage cp.async K/V ring.
// Smem: Q 16KB + 4 x 16KB = 80KB.
// ---------------------------------------------------------------------------
__global__ __launch_bounds__(128, 2) void attn_h()
{
    extern __shared__ char smc[];
    const uint32_t smu = smem_u32(smc);
    const uint32_t Qs = smu;                      // 128 rows x 128B

    const int tid = threadIdx.x, w = tid >> 5, lane = tid & 31;
    const int gi = lane >> 2, tg = lane & 3;
    const int rw = lane & 7, bq = lane >> 3;
    const int qt = blockIdx.x, h = blockIdx.y, b = blockIdx.z;
    const int bh = (b << 4) + h;
    const uint32_t ONES = 0x3C003C00u;            // half2(1.0, 1.0)

    const __half* Qg = g_Qh + ((size_t)bh * SEQ + (qt << 7)) * DH;
    const __half* Kg = g_Kh + (size_t)bh * SEQ * DH;
    const __half* Vg = g_Vh + (size_t)bh * SEQ * DH;

    // Q: 1024 granules of 16B, 128 threads -> 8 each (group 0)
#pragma unroll
    for (int i = 0; i < 8; ++i) {
        int g = tid + (i << 7);
        int row = g >> 3, ch = g & 7;
        cp16(Qs + row * 128 + ((uint32_t)(ch ^ (row & 7)) << 4),
             Qg + (size_t)row * 64 + ch * 8);
    }
    CP_COMMIT();

    auto load_kv = [&](int st, int kt) {
        uint32_t Kb = smu + 16384 + st * 16384;
        uint32_t Vb = Kb + 8192;
        const __half* kp = Kg + (size_t)(kt << 6) * DH;
        const __half* vp = Vg + (size_t)(kt << 6) * DH;
#pragma unroll
        for (int i = 0; i < 4; ++i) {
            int g = tid + (i << 7);             // 0..511
            int row = g >> 3, ch = g & 7;
            uint32_t sw = (uint32_t)(ch ^ (row & 7)) << 4;
            cp16(Kb + row * 128 + sw, kp + (size_t)row * 64 + ch * 8);
            cp16(Vb + row * 128 + sw, vp + (size_t)row * 64 + ch * 8);
        }
        CP_COMMIT();
    };
    load_kv(0, 0);
    load_kv(1, 1);
    load_kv(2, 2);

    CP_WAIT(3);            // Q group complete (kv0..kv2 may still be in flight)
    __syncthreads();

    // Hoist Q fragments: two m16 tiles per warp (rows w*32 + mf*16 + ...)
    uint32_t Aq[2][4][4];
#pragma unroll
    for (int mf = 0; mf < 2; ++mf)
#pragma unroll
        for (int kc = 0; kc < 4; ++kc) {
            int row = w * 32 + mf * 16 + (bq & 1) * 8 + rw;
            int kch = kc * 2 + (bq >> 1);
            LDSM4(Aq[mf][kc][0], Aq[mf][kc][1], Aq[mf][kc][2], Aq[mf][kc][3],
                  Qs + row * 128 + ((uint32_t)(kch ^ (row & 7)) << 4));
        }

    float O[2][8][4] = {};
    float L[2][4] = {};     // ones-mma row sums per m-tile

    for (int t = 0; t < 32; ++t) {
        if (t < 30)      { CP_WAIT(2); }
        else if (t == 30){ CP_WAIT(1); }
        else             { CP_WAIT(0); }
        __syncthreads();
        if (t + 3 < 32) load_kv((t + 3) & 3, t + 3);

        uint32_t Kb = smu + 16384 + (t & 3) * 16384;
        uint32_t Vb = Kb + 8192;

        // S = Qhat @ K^T (log2 domain; 4 k16-steps, 8 n-tiles, 2 m-tiles)
        float S[2][8][4] = {};
#pragma unroll
        for (int kc = 0; kc < 4; ++kc) {
            uint32_t bK[8][2];
#pragma unroll
            for (int np = 0; np < 4; ++np) {
                int row = np * 16 + (bq >> 1) * 8 + rw;
                int kch = kc * 2 + (bq & 1);
                LDSM4(bK[2*np][0], bK[2*np][1], bK[2*np+1][0], bK[2*np+1][1],
                      Kb + row * 128 + ((uint32_t)(kch ^ (row & 7)) << 4));
            }
#pragma unroll
            for (int nf = 0; nf < 8; ++nf) {
                mma16(S[0][nf], Aq[0][kc], bK[nf][0], bK[nf][1]);
                mma16(S[1][nf], Aq[1][kc], bK[nf][0], bK[nf][1]);
            }
        }

        // P = exp2(S) per kc; L += P @ ones; O += P @ V (V frags shared by
        // both m-tiles -> halved LDSM per mma).
#pragma unroll
        for (int kc = 0; kc < 4; ++kc) {
            uint32_t Ap[2][4];
#pragma unroll
            for (int mf = 0; mf < 2; ++mf) {
                Ap[mf][0] = packh2(ex2(S[mf][2*kc][0]),   ex2(S[mf][2*kc][1]));
                Ap[mf][1] = packh2(ex2(S[mf][2*kc][2]),   ex2(S[mf][2*kc][3]));
                Ap[mf][2] = packh2(ex2(S[mf][2*kc+1][0]), ex2(S[mf][2*kc+1][1]));
                Ap[mf][3] = packh2(ex2(S[mf][2*kc+1][2]), ex2(S[mf][2*kc+1][3]));
                mma16(L[mf], Ap[mf], ONES, ONES);
            }
#pragma unroll
            for (int dp = 0; dp < 4; ++dp) {
                uint32_t r0, r1, r2, r3;
                int krow = kc * 16 + (bq & 1) * 8 + rw;
                int dch = dp * 2 + (bq >> 1);
                LDSM4T(r0, r1, r2, r3,
                       Vb + krow * 128 + ((uint32_t)(dch ^ (krow & 7)) << 4));
                mma16(O[0][2*dp],     Ap[0], r0, r1);
                mma16(O[0][2*dp + 1], Ap[0], r2, r3);
                mma16(O[1][2*dp],     Ap[1], r0, r1);
                mma16(O[1][2*dp + 1], Ap[1], r2, r3);
            }
        }
    }

    // Normalize, store ctx (fp16, head-merged [B,S,D])
#pragma unroll
    for (int mf = 0; mf < 2; ++mf) {
        float inv0 = 1.0f / L[mf][0], inv1 = 1.0f / L[mf][2];
        int r = (qt << 7) + w * 32 + mf * 16 + gi;
        __half* d0 = g_ctxh + ((size_t)b * SEQ + r) * DMODEL + (h << 6);
        __half* d1 = d0 + 8 * DMODEL;
#pragma unroll
        for (int nf = 0; nf < 8; ++nf) {
            *(half2*)(d0 + nf * 8 + 2 * tg) = __floats2half2_rn(O[mf][nf][0] * inv0, O[mf][nf][1] * inv0);
            *(half2*)(d1 + nf * 8 + 2 * tg) = __floats2half2_rn(O[mf][nf][2] * inv1, O[mf][nf][3] * inv1);
        }
    }
}

// ---------------------------------------------------------------------------
extern "C" void kernel_launch(void* const* d_in, const int* in_sizes, int n_in,
                              void* d_out, int out_size)
{
    const float* x  = (const float*)d_in[0];
    const float* Wq = (const float*)d_in[1];
    const float* Wk = (const float*)d_in[2];
    const float* Wv = (const float*)d_in[3];
    const float* Wo = (const float*)d_in[4];
    float* out = (float*)d_out;

    const int GEMM_SMEM = 3 * GSTG;            // 98304 B
    const int ATTN_SMEM = 16384 + 4 * 16384;   // 81920 B
    static int inited = 0;
    if (!inited) {
        cudaFuncSetAttribute(gemm_h, cudaFuncAttributeMaxDynamicSharedMemorySize, GEMM_SMEM);
        cudaFuncSetAttribute(attn_h, cudaFuncAttributeMaxDynamicSharedMemorySize, ATTN_SMEM);
        inited = 1;
    }

    // device-pointer fetches for __device__ globals used as kernel args
    __half *xh, *wqh, *wkh, *wvh, *woh, *ctxh;
    cudaGetSymbolAddress((void**)&xh,   g_xh);
    cudaGetSymbolAddress((void**)&wqh,  g_Wqh);
    cudaGetSymbolAddress((void**)&wkh,  g_Wkh);
    cudaGetSymbolAddress((void**)&wvh,  g_Wvh);
    cudaGetSymbolAddress((void**)&woh,  g_Woh);
    cudaGetSymbolAddress((void**)&ctxh, g_ctxh);

    cvt_init<<<dim3(1024, 1, 9), 256>>>(x, Wq, Wk, Wv, Wo);
    // fused Q/K/V projections: z = mode 0,1,2
    gemm_h<<<dim3(8, 32, 3), 256, GEMM_SMEM>>>(xh, wqh, wkh, wvh, nullptr, 0);
    attn_h<<<dim3(16, NH, NB), 128, ATTN_SMEM>>>();
    gemm_h<<<dim3(8, 32, 1), 256, GEMM_SMEM>>>(ctxh, woh, nullptr, nullptr, out, 3);
}